// round 1
// baseline (speedup 1.0000x reference)
#include <cuda_runtime.h>
#include <math.h>

// ---------------- scratch buffers (static device memory, no allocs) ----------
#define NTOK 4096              // 4 * 1024 rows
#define HID  1024
__device__ float g_Q [NTOK * HID];
__device__ float g_K [NTOK * HID];
__device__ float g_V [NTOK * HID];
__device__ float g_O [NTOK * HID];
__device__ float g_X1[NTOK * HID];
__device__ float g_F [NTOK * HID];
__device__ float g_Hb[NTOK * 4 * HID];

// ---------------- tiled fp32 GEMM: C = act(A[MxK] @ B[KxN] + bias) ----------
// BM=BN=128, BK=8, 256 threads, 8x8 per thread, register prefetch.
__global__ __launch_bounds__(256) void gemm_bias_kernel(
    const float* __restrict__ A, const float* __restrict__ B,
    const float* __restrict__ bias, float* __restrict__ C,
    int M, int N, int K, int act)
{
    __shared__ float As[8][128];
    __shared__ float Bs[8][128];

    const int tid = threadIdx.x;
    const int bm = blockIdx.y * 128;
    const int bn = blockIdx.x * 128;

    // A loader: 128 rows x 8 cols = 256 float4 (2 per row along K)
    const int arow = tid >> 1;
    const int aseg = (tid & 1) * 4;
    // B loader: 8 rows x 128 cols = 256 float4
    const int brow = tid >> 5;
    const int bcol = (tid & 31) * 4;

    const float* Aptr = A + (size_t)(bm + arow) * K + aseg;
    const float* Bptr = B + (size_t)brow * N + bn + bcol;

    const int tx = tid & 15, ty = tid >> 4;
    const int rm0 = ty * 4, rm1 = 64 + ty * 4;
    const int cn0 = tx * 4, cn1 = 64 + tx * 4;

    float acc[8][8];
    #pragma unroll
    for (int i = 0; i < 8; ++i)
        #pragma unroll
        for (int j = 0; j < 8; ++j) acc[i][j] = 0.f;

    const int ntiles = K >> 3;
    float4 pa = *(const float4*)(Aptr);
    float4 pb = *(const float4*)(Bptr);

    for (int t = 0; t < ntiles; ++t) {
        As[aseg + 0][arow] = pa.x;
        As[aseg + 1][arow] = pa.y;
        As[aseg + 2][arow] = pa.z;
        As[aseg + 3][arow] = pa.w;
        *(float4*)&Bs[brow][bcol] = pb;
        __syncthreads();

        if (t + 1 < ntiles) {
            pa = *(const float4*)(Aptr + (size_t)(t + 1) * 8);
            pb = *(const float4*)(Bptr + (size_t)(t + 1) * 8 * N);
        }

        #pragma unroll
        for (int k = 0; k < 8; ++k) {
            float4 a0 = *(const float4*)&As[k][rm0];
            float4 a1 = *(const float4*)&As[k][rm1];
            float4 b0 = *(const float4*)&Bs[k][cn0];
            float4 b1 = *(const float4*)&Bs[k][cn1];
            float ar[8] = {a0.x, a0.y, a0.z, a0.w, a1.x, a1.y, a1.z, a1.w};
            float br[8] = {b0.x, b0.y, b0.z, b0.w, b1.x, b1.y, b1.z, b1.w};
            #pragma unroll
            for (int i = 0; i < 8; ++i)
                #pragma unroll
                for (int j = 0; j < 8; ++j)
                    acc[i][j] = fmaf(ar[i], br[j], acc[i][j]);
        }
        __syncthreads();
    }

    // epilogue
    #pragma unroll
    for (int i = 0; i < 8; ++i) {
        int row = bm + ((i < 4) ? (rm0 + i) : (rm1 + i - 4));
        #pragma unroll
        for (int half = 0; half < 2; ++half) {
            int col = bn + (half ? cn1 : cn0);
            float4 r;
            r.x = acc[i][half * 4 + 0] + bias[col + 0];
            r.y = acc[i][half * 4 + 1] + bias[col + 1];
            r.z = acc[i][half * 4 + 2] + bias[col + 2];
            r.w = acc[i][half * 4 + 3] + bias[col + 3];
            if (act) {
                r.x = 0.5f * r.x * (1.f + erff(r.x * 0.70710678118654752f));
                r.y = 0.5f * r.y * (1.f + erff(r.y * 0.70710678118654752f));
                r.z = 0.5f * r.z * (1.f + erff(r.z * 0.70710678118654752f));
                r.w = 0.5f * r.w * (1.f + erff(r.w * 0.70710678118654752f));
            }
            *(float4*)&C[(size_t)row * N + col] = r;
        }
    }
}

// ---------------- fused attention with head-axis softmax ---------------------
// q[n,h,t,d] = Q[n, h*64 + t/16, (t%16)*64 + d]  (raw reshape semantics)
// grid = (a=64, n=4), block = 256 threads = (h = tid/16, b = tid%16)
// smem: buf[16][1024] (K rows, then reused for V rows), sc[16][16][17 padded]
#define SC(h, b, bp) ((h) * 272 + (b) * 17 + (bp))

__global__ __launch_bounds__(256, 1) void attn_kernel(
    const float* __restrict__ Q, const float* __restrict__ K,
    const float* __restrict__ V, float* __restrict__ O)
{
    extern __shared__ float sm[];
    float* buf = sm;            // 16*1024 floats
    float* sc  = sm + 16 * 1024; // 16*272 floats

    const int tid = threadIdx.x;
    const int h = tid >> 4, b = tid & 15;
    const int a = blockIdx.x;
    const int n = blockIdx.y;
    const float scale = 0.03125f; // 1/sqrt(1024)

    const size_t base_n = (size_t)n * 1024 * 1024;

    // q for this (h, b): 64 floats, kept in registers for the whole block
    float4 qr[16];
    {
        const float* qrow = Q + base_n + (size_t)(h * 64 + a) * 1024 + b * 64;
        #pragma unroll
        for (int i = 0; i < 16; ++i) qr[i] = *(const float4*)(qrow + i * 4);
    }

    float4 acc[16];
    #pragma unroll
    for (int i = 0; i < 16; ++i) acc[i] = make_float4(0.f, 0.f, 0.f, 0.f);

    for (int ap = 0; ap < 64; ++ap) {
        __syncthreads();  // prev AV done with buf / sc

        // stage K rows (head i -> row i*64 + ap)
        #pragma unroll
        for (int i = 0; i < 16; ++i)
            *(float4*)&buf[i * 1024 + tid * 4] =
                *(const float4*)(K + base_n + (size_t)(i * 64 + ap) * 1024 + tid * 4);
        __syncthreads();

        // scores: thread (h,b) computes 16 b' dot products (k via smem broadcast)
        {
            const float* kh = buf + h * 1024;
            #pragma unroll
            for (int bp = 0; bp < 16; ++bp) {
                float s = 0.f;
                #pragma unroll
                for (int j = 0; j < 16; ++j) {
                    float4 kv = *(const float4*)(kh + bp * 64 + j * 4);
                    s = fmaf(qr[j].x, kv.x, s);
                    s = fmaf(qr[j].y, kv.y, s);
                    s = fmaf(qr[j].z, kv.z, s);
                    s = fmaf(qr[j].w, kv.w, s);
                }
                sc[SC(h, b, bp)] = s * scale;
            }
        }
        __syncthreads();

        // stage V rows into buf while doing the head-softmax on sc
        #pragma unroll
        for (int i = 0; i < 16; ++i)
            *(float4*)&buf[i * 1024 + tid * 4] =
                *(const float4*)(V + base_n + (size_t)(i * 64 + ap) * 1024 + tid * 4);

        {   // thread p owns (b = p/16, b' = p%16): softmax over the 16 heads
            const int pb = tid >> 4, pbp = tid & 15;
            float m = -1e30f;
            #pragma unroll
            for (int hh = 0; hh < 16; ++hh) m = fmaxf(m, sc[SC(hh, pb, pbp)]);
            float e[16], ssum = 0.f;
            #pragma unroll
            for (int hh = 0; hh < 16; ++hh) {
                e[hh] = __expf(sc[SC(hh, pb, pbp)] - m);
                ssum += e[hh];
            }
            float inv = 1.f / ssum;
            #pragma unroll
            for (int hh = 0; hh < 16; ++hh) sc[SC(hh, pb, pbp)] = e[hh] * inv;
        }
        __syncthreads();

        // AV accumulate
        {
            const float* vh = buf + h * 1024;
            #pragma unroll
            for (int bp = 0; bp < 16; ++bp) {
                float w = sc[SC(h, b, bp)];
                #pragma unroll
                for (int j = 0; j < 16; ++j) {
                    float4 vv = *(const float4*)(vh + bp * 64 + j * 4);
                    acc[j].x = fmaf(w, vv.x, acc[j].x);
                    acc[j].y = fmaf(w, vv.y, acc[j].y);
                    acc[j].z = fmaf(w, vv.z, acc[j].z);
                    acc[j].w = fmaf(w, vv.w, acc[j].w);
                }
            }
        }
    }

    float* orow = O + base_n + (size_t)(h * 64 + a) * 1024 + b * 64;
    #pragma unroll
    for (int i = 0; i < 16; ++i) *(float4*)(orow + i * 4) = acc[i];
}

// ---------------- fused residual + LayerNorm ---------------------------------
__global__ __launch_bounds__(256) void ln_kernel(
    const float* __restrict__ A, const float* __restrict__ R,
    const float* __restrict__ g, const float* __restrict__ bta,
    float* __restrict__ out)
{
    __shared__ float red[16];
    const int row = blockIdx.x;
    const int tid = threadIdx.x;

    float4 v = ((const float4*)(A + (size_t)row * 1024))[tid];
    float4 r = ((const float4*)(R + (size_t)row * 1024))[tid];
    v.x += r.x; v.y += r.y; v.z += r.z; v.w += r.w;

    float s  = v.x + v.y + v.z + v.w;
    float sq = v.x * v.x + v.y * v.y + v.z * v.z + v.w * v.w;
    #pragma unroll
    for (int o = 16; o > 0; o >>= 1) {
        s  += __shfl_xor_sync(0xffffffffu, s,  o);
        sq += __shfl_xor_sync(0xffffffffu, sq, o);
    }
    if ((tid & 31) == 0) { red[tid >> 5] = s; red[8 + (tid >> 5)] = sq; }
    __syncthreads();
    float S = 0.f, SQ = 0.f;
    #pragma unroll
    for (int w = 0; w < 8; ++w) { S += red[w]; SQ += red[8 + w]; }

    const float mean = S * (1.f / 1024.f);
    const float var  = SQ * (1.f / 1024.f) - mean * mean;
    const float rstd = rsqrtf(var + 1e-5f);

    float4 gv = ((const float4*)g)[tid];
    float4 bv = ((const float4*)bta)[tid];
    float4 o;
    o.x = (v.x - mean) * rstd * gv.x + bv.x;
    o.y = (v.y - mean) * rstd * gv.y + bv.y;
    o.z = (v.z - mean) * rstd * gv.z + bv.z;
    o.w = (v.w - mean) * rstd * gv.w + bv.w;
    ((float4*)(out + (size_t)row * 1024))[tid] = o;
}

// ---------------- launch ------------------------------------------------------
extern "C" void kernel_launch(void* const* d_in, const int* in_sizes, int n_in,
                              void* d_out, int out_size)
{
    const float* x  = (const float*)d_in[0];
    const float* Wq = (const float*)d_in[1];
    const float* bq = (const float*)d_in[2];
    const float* Wk = (const float*)d_in[3];
    const float* bk = (const float*)d_in[4];
    const float* Wv = (const float*)d_in[5];
    const float* bv = (const float*)d_in[6];
    const float* Wo = (const float*)d_in[7];
    const float* bo = (const float*)d_in[8];
    const float* g1 = (const float*)d_in[9];
    const float* b1 = (const float*)d_in[10];
    const float* W1 = (const float*)d_in[11];
    const float* c1 = (const float*)d_in[12];
    const float* W2 = (const float*)d_in[13];
    const float* c2 = (const float*)d_in[14];
    const float* g2 = (const float*)d_in[15];
    const float* b2 = (const float*)d_in[16];
    float* out = (float*)d_out;

    float *pQ, *pK, *pV, *pO, *pX1, *pF, *pH;
    cudaGetSymbolAddress((void**)&pQ,  g_Q);
    cudaGetSymbolAddress((void**)&pK,  g_K);
    cudaGetSymbolAddress((void**)&pV,  g_V);
    cudaGetSymbolAddress((void**)&pO,  g_O);
    cudaGetSymbolAddress((void**)&pX1, g_X1);
    cudaGetSymbolAddress((void**)&pF,  g_F);
    cudaGetSymbolAddress((void**)&pH,  g_Hb);

    const int ATTN_SMEM = (16 * 1024 + 16 * 272) * 4; // 82944 bytes
    cudaFuncSetAttribute(attn_kernel, cudaFuncAttributeMaxDynamicSharedMemorySize, ATTN_SMEM);

    dim3 blk(256);
    dim3 g_h1(HID / 128, NTOK / 128);      // N=1024 output
    dim3 g_h4(4 * HID / 128, NTOK / 128);  // N=4096 output

    // QKV projections
    gemm_bias_kernel<<<g_h1, blk>>>(x, Wq, bq, pQ, NTOK, HID, HID, 0);
    gemm_bias_kernel<<<g_h1, blk>>>(x, Wk, bk, pK, NTOK, HID, HID, 0);
    gemm_bias_kernel<<<g_h1, blk>>>(x, Wv, bv, pV, NTOK, HID, HID, 0);

    // fused attention (head-axis softmax)
    attn_kernel<<<dim3(64, 4), blk, ATTN_SMEM>>>(pQ, pK, pV, pO);

    // output projection, residual + LN1
    gemm_bias_kernel<<<g_h1, blk>>>(pO, Wo, bo, pF, NTOK, HID, HID, 0);
    ln_kernel<<<NTOK, blk>>>(pF, x, g1, b1, pX1);

    // FFN
    gemm_bias_kernel<<<g_h4, blk>>>(pX1, W1, c1, pH, NTOK, 4 * HID, HID, 1);
    gemm_bias_kernel<<<g_h1, blk>>>(pH, W2, c2, pF, NTOK, HID, 4 * HID, 0);

    // residual + LN2 -> output
    ln_kernel<<<NTOK, blk>>>(pF, pX1, g2, b2, out);
}

// round 2
// speedup vs baseline: 1.0156x; 1.0156x over previous
#include <cuda_runtime.h>
#include <math.h>

// ---------------- scratch buffers (static device memory, no allocs) ----------
#define NTOK 4096              // 4 * 1024 rows
#define HID  1024
__device__ float g_Q [NTOK * HID];
__device__ float g_K [NTOK * HID];
__device__ float g_V [NTOK * HID];
__device__ float g_O [NTOK * HID];
__device__ float g_X1[NTOK * HID];
__device__ float g_F [NTOK * HID];
__device__ float g_Hb[NTOK * 4 * HID];

// ---------------- packed f32x2 helpers ---------------------------------------
#define FMA2(d, a, b) \
    asm("fma.rn.f32x2 %0, %1, %2, %0;" : "+l"(d) : "l"(a), "l"(b))
#define PACK2(out, x, y) \
    asm("mov.b64 %0, {%1, %2};" : "=l"(out) : "f"(x), "f"(y))
#define UNPACK2(lo, hi, in) \
    asm("mov.b64 {%0, %1}, %2;" : "=f"(lo), "=f"(hi) : "l"(in))

// ---------------- tiled fp32 GEMM: C = act(A[MxK] @ B[KxN] + bias) ----------
// BM=BN=128, BK=8, 256 threads, 8x8 per thread, FFMA2 inner product.
__global__ __launch_bounds__(256) void gemm_bias_kernel(
    const float* __restrict__ A, const float* __restrict__ B,
    const float* __restrict__ bias, float* __restrict__ C,
    int M, int N, int K, int act)
{
    __shared__ float As[8][128];
    __shared__ float Bs[8][128];

    const int tid = threadIdx.x;
    const int bm = blockIdx.y * 128;
    const int bn = blockIdx.x * 128;

    const int arow = tid >> 1;
    const int aseg = (tid & 1) * 4;
    const int brow = tid >> 5;
    const int bcol = (tid & 31) * 4;

    const float* Aptr = A + (size_t)(bm + arow) * K + aseg;
    const float* Bptr = B + (size_t)brow * N + bn + bcol;

    const int tx = tid & 15, ty = tid >> 4;
    const int rm0 = ty * 4, rm1 = 64 + ty * 4;
    const int cn0 = tx * 4, cn1 = 64 + tx * 4;

    unsigned long long acc2[8][4];
    #pragma unroll
    for (int i = 0; i < 8; ++i)
        #pragma unroll
        for (int j = 0; j < 4; ++j) acc2[i][j] = 0ULL;

    const int ntiles = K >> 3;
    float4 pa = *(const float4*)(Aptr);
    float4 pb = *(const float4*)(Bptr);

    for (int t = 0; t < ntiles; ++t) {
        As[aseg + 0][arow] = pa.x;
        As[aseg + 1][arow] = pa.y;
        As[aseg + 2][arow] = pa.z;
        As[aseg + 3][arow] = pa.w;
        *(float4*)&Bs[brow][bcol] = pb;
        __syncthreads();

        if (t + 1 < ntiles) {
            pa = *(const float4*)(Aptr + (size_t)(t + 1) * 8);
            pb = *(const float4*)(Bptr + (size_t)(t + 1) * 8 * N);
        }

        #pragma unroll
        for (int k = 0; k < 8; ++k) {
            float4 a0 = *(const float4*)&As[k][rm0];
            float4 a1 = *(const float4*)&As[k][rm1];
            ulonglong2 bb0 = *(const ulonglong2*)&Bs[k][cn0];
            ulonglong2 bb1 = *(const ulonglong2*)&Bs[k][cn1];
            float ar[8] = {a0.x, a0.y, a0.z, a0.w, a1.x, a1.y, a1.z, a1.w};
            unsigned long long bp2[4] = {bb0.x, bb0.y, bb1.x, bb1.y};
            #pragma unroll
            for (int i = 0; i < 8; ++i) {
                unsigned long long ad;
                PACK2(ad, ar[i], ar[i]);
                #pragma unroll
                for (int jp = 0; jp < 4; ++jp)
                    FMA2(acc2[i][jp], ad, bp2[jp]);
            }
        }
        __syncthreads();
    }

    // epilogue
    #pragma unroll
    for (int i = 0; i < 8; ++i) {
        int row = bm + ((i < 4) ? (rm0 + i) : (rm1 + i - 4));
        #pragma unroll
        for (int half = 0; half < 2; ++half) {
            int col = bn + (half ? cn1 : cn0);
            float c0, c1, c2, c3;
            UNPACK2(c0, c1, acc2[i][half * 2 + 0]);
            UNPACK2(c2, c3, acc2[i][half * 2 + 1]);
            float4 r;
            r.x = c0 + bias[col + 0];
            r.y = c1 + bias[col + 1];
            r.z = c2 + bias[col + 2];
            r.w = c3 + bias[col + 3];
            if (act) {
                r.x = 0.5f * r.x * (1.f + erff(r.x * 0.70710678118654752f));
                r.y = 0.5f * r.y * (1.f + erff(r.y * 0.70710678118654752f));
                r.z = 0.5f * r.z * (1.f + erff(r.z * 0.70710678118654752f));
                r.w = 0.5f * r.w * (1.f + erff(r.w * 0.70710678118654752f));
            }
            *(float4*)&C[(size_t)row * N + col] = r;
        }
    }
}

// ---------------- fused attention with head-axis softmax ---------------------
// q[n,h,t,d] = Q[n, h*64 + t/16, (t%16)*64 + d]  (raw reshape semantics)
// grid = (a=64, n=4), block = 256 threads:
//   h  = tid>>4      (head, 16)
//   bg = (tid>>2)&3  (group of 4 b-values)
//   dq = tid&3       (d-lane: owns 16 of 64 d, chunk-interleaved c = dq + 4m)
// Each thread holds q and o for 4 b-rows x 16 d -> every smem K/V float4 feeds
// 4 FMAs x 4 b = 4x traffic reduction vs 1-b-per-thread. Partial dots are
// combined across the 4 dq lanes with 2 xor-shuffles.
// smem: buf[16][1040] K/V rows (padded vs head-stride conflicts), sc[16][16][17]
#define SC(h, b, bp) ((h) * 272 + (b) * 17 + (bp))
#define BUFSTRIDE 1040

__global__ __launch_bounds__(256, 1) void attn_kernel(
    const float* __restrict__ Q, const float* __restrict__ K,
    const float* __restrict__ V, float* __restrict__ O)
{
    extern __shared__ float sm[];
    float* buf = sm;                       // 16*1040 floats
    float* sc  = sm + 16 * BUFSTRIDE;      // 16*272 floats

    const int tid = threadIdx.x;
    const int h  = tid >> 4;
    const int bg = (tid >> 2) & 3;
    const int dq = tid & 3;
    const int a = blockIdx.x;
    const int n = blockIdx.y;
    const float scale = 0.03125f; // 1/sqrt(1024)

    const size_t base_n = (size_t)n * 1024 * 1024;

    // q (scaled) for 4 b-rows, 16 d each, as 8 f32x2 pairs per row
    unsigned long long q2[4][8];
    #pragma unroll
    for (int i = 0; i < 4; ++i) {
        const float* qrow = Q + base_n + (size_t)(h * 64 + a) * 1024
                              + (bg * 4 + i) * 64;
        #pragma unroll
        for (int m = 0; m < 4; ++m) {
            float4 t = *(const float4*)(qrow + dq * 4 + m * 16);
            t.x *= scale; t.y *= scale; t.z *= scale; t.w *= scale;
            PACK2(q2[i][m * 2 + 0], t.x, t.y);
            PACK2(q2[i][m * 2 + 1], t.z, t.w);
        }
    }

    unsigned long long acc2[4][8];
    #pragma unroll
    for (int i = 0; i < 4; ++i)
        #pragma unroll
        for (int p = 0; p < 8; ++p) acc2[i][p] = 0ULL;

    for (int ap = 0; ap < 64; ++ap) {
        __syncthreads();  // prev AV done with buf / sc

        // stage K rows (head i -> row i*64 + ap)
        #pragma unroll
        for (int i = 0; i < 16; ++i)
            *(float4*)&buf[i * BUFSTRIDE + tid * 4] =
                *(const float4*)(K + base_n + (size_t)(i * 64 + ap) * 1024 + tid * 4);
        __syncthreads();

        // scores
        {
            const float* kh = buf + h * BUFSTRIDE;
            #pragma unroll
            for (int bp = 0; bp < 16; ++bp) {
                unsigned long long kp[8];
                #pragma unroll
                for (int m = 0; m < 4; ++m) {
                    ulonglong2 kv = *(const ulonglong2*)(kh + bp * 64 + dq * 4 + m * 16);
                    kp[m * 2 + 0] = kv.x;
                    kp[m * 2 + 1] = kv.y;
                }
                unsigned long long s2[4] = {0ULL, 0ULL, 0ULL, 0ULL};
                #pragma unroll
                for (int p = 0; p < 8; ++p)
                    #pragma unroll
                    for (int i = 0; i < 4; ++i)
                        FMA2(s2[i], q2[i][p], kp[p]);

                float sf[4];
                #pragma unroll
                for (int i = 0; i < 4; ++i) {
                    float lo, hi;
                    UNPACK2(lo, hi, s2[i]);
                    sf[i] = lo + hi;
                    sf[i] += __shfl_xor_sync(0xffffffffu, sf[i], 1);
                    sf[i] += __shfl_xor_sync(0xffffffffu, sf[i], 2);
                }
                // lane dq stores the score for b = bg*4 + dq
                float myv = (dq == 0) ? sf[0] : (dq == 1) ? sf[1]
                          : (dq == 2) ? sf[2] : sf[3];
                sc[SC(h, bg * 4 + dq, bp)] = myv;
            }
        }
        __syncthreads();

        // stage V rows into buf while doing the head-softmax on sc
        #pragma unroll
        for (int i = 0; i < 16; ++i)
            *(float4*)&buf[i * BUFSTRIDE + tid * 4] =
                *(const float4*)(V + base_n + (size_t)(i * 64 + ap) * 1024 + tid * 4);

        {   // thread p owns (b = p/16, b' = p%16): softmax over the 16 heads
            const int pb = tid >> 4, pbp = tid & 15;
            float m = -1e30f;
            #pragma unroll
            for (int hh = 0; hh < 16; ++hh) m = fmaxf(m, sc[SC(hh, pb, pbp)]);
            float e[16], ssum = 0.f;
            #pragma unroll
            for (int hh = 0; hh < 16; ++hh) {
                e[hh] = __expf(sc[SC(hh, pb, pbp)] - m);
                ssum += e[hh];
            }
            float inv = 1.f / ssum;
            #pragma unroll
            for (int hh = 0; hh < 16; ++hh) sc[SC(hh, pb, pbp)] = e[hh] * inv;
        }
        __syncthreads();

        // AV accumulate
        {
            const float* vh = buf + h * BUFSTRIDE;
            #pragma unroll
            for (int bp = 0; bp < 16; ++bp) {
                unsigned long long vp[8];
                #pragma unroll
                for (int m = 0; m < 4; ++m) {
                    ulonglong2 vv = *(const ulonglong2*)(vh + bp * 64 + dq * 4 + m * 16);
                    vp[m * 2 + 0] = vv.x;
                    vp[m * 2 + 1] = vv.y;
                }
                #pragma unroll
                for (int i = 0; i < 4; ++i) {
                    float w = sc[SC(h, bg * 4 + i, bp)];
                    unsigned long long w2;
                    PACK2(w2, w, w);
                    #pragma unroll
                    for (int p = 0; p < 8; ++p)
                        FMA2(acc2[i][p], w2, vp[p]);
                }
            }
        }
    }

    #pragma unroll
    for (int i = 0; i < 4; ++i) {
        float* orow = O + base_n + (size_t)(h * 64 + a) * 1024 + (bg * 4 + i) * 64;
        #pragma unroll
        for (int m = 0; m < 4; ++m) {
            ulonglong2 ov;
            ov.x = acc2[i][m * 2 + 0];
            ov.y = acc2[i][m * 2 + 1];
            *(ulonglong2*)(orow + dq * 4 + m * 16) = ov;
        }
    }
}

// ---------------- fused residual + LayerNorm ---------------------------------
__global__ __launch_bounds__(256) void ln_kernel(
    const float* __restrict__ A, const float* __restrict__ R,
    const float* __restrict__ g, const float* __restrict__ bta,
    float* __restrict__ out)
{
    __shared__ float red[16];
    const int row = blockIdx.x;
    const int tid = threadIdx.x;

    float4 v = ((const float4*)(A + (size_t)row * 1024))[tid];
    float4 r = ((const float4*)(R + (size_t)row * 1024))[tid];
    v.x += r.x; v.y += r.y; v.z += r.z; v.w += r.w;

    float s  = v.x + v.y + v.z + v.w;
    float sq = v.x * v.x + v.y * v.y + v.z * v.z + v.w * v.w;
    #pragma unroll
    for (int o = 16; o > 0; o >>= 1) {
        s  += __shfl_xor_sync(0xffffffffu, s,  o);
        sq += __shfl_xor_sync(0xffffffffu, sq, o);
    }
    if ((tid & 31) == 0) { red[tid >> 5] = s; red[8 + (tid >> 5)] = sq; }
    __syncthreads();
    float S = 0.f, SQ = 0.f;
    #pragma unroll
    for (int w = 0; w < 8; ++w) { S += red[w]; SQ += red[8 + w]; }

    const float mean = S * (1.f / 1024.f);
    const float var  = SQ * (1.f / 1024.f) - mean * mean;
    const float rstd = rsqrtf(var + 1e-5f);

    float4 gv = ((const float4*)g)[tid];
    float4 bv = ((const float4*)bta)[tid];
    float4 o;
    o.x = (v.x - mean) * rstd * gv.x + bv.x;
    o.y = (v.y - mean) * rstd * gv.y + bv.y;
    o.z = (v.z - mean) * rstd * gv.z + bv.z;
    o.w = (v.w - mean) * rstd * gv.w + bv.w;
    ((float4*)(out + (size_t)row * 1024))[tid] = o;
}

// ---------------- launch ------------------------------------------------------
extern "C" void kernel_launch(void* const* d_in, const int* in_sizes, int n_in,
                              void* d_out, int out_size)
{
    const float* x  = (const float*)d_in[0];
    const float* Wq = (const float*)d_in[1];
    const float* bq = (const float*)d_in[2];
    const float* Wk = (const float*)d_in[3];
    const float* bk = (const float*)d_in[4];
    const float* Wv = (const float*)d_in[5];
    const float* bv = (const float*)d_in[6];
    const float* Wo = (const float*)d_in[7];
    const float* bo = (const float*)d_in[8];
    const float* g1 = (const float*)d_in[9];
    const float* b1 = (const float*)d_in[10];
    const float* W1 = (const float*)d_in[11];
    const float* c1 = (const float*)d_in[12];
    const float* W2 = (const float*)d_in[13];
    const float* c2 = (const float*)d_in[14];
    const float* g2 = (const float*)d_in[15];
    const float* b2 = (const float*)d_in[16];
    float* out = (float*)d_out;

    float *pQ, *pK, *pV, *pO, *pX1, *pF, *pH;
    cudaGetSymbolAddress((void**)&pQ,  g_Q);
    cudaGetSymbolAddress((void**)&pK,  g_K);
    cudaGetSymbolAddress((void**)&pV,  g_V);
    cudaGetSymbolAddress((void**)&pO,  g_O);
    cudaGetSymbolAddress((void**)&pX1, g_X1);
    cudaGetSymbolAddress((void**)&pF,  g_F);
    cudaGetSymbolAddress((void**)&pH,  g_Hb);

    const int ATTN_SMEM = (16 * BUFSTRIDE + 16 * 272) * 4; // 83968 bytes
    cudaFuncSetAttribute(attn_kernel, cudaFuncAttributeMaxDynamicSharedMemorySize, ATTN_SMEM);

    dim3 blk(256);
    dim3 g_h1(HID / 128, NTOK / 128);      // N=1024 output
    dim3 g_h4(4 * HID / 128, NTOK / 128);  // N=4096 output

    // QKV projections
    gemm_bias_kernel<<<g_h1, blk>>>(x, Wq, bq, pQ, NTOK, HID, HID, 0);
    gemm_bias_kernel<<<g_h1, blk>>>(x, Wk, bk, pK, NTOK, HID, HID, 0);
    gemm_bias_kernel<<<g_h1, blk>>>(x, Wv, bv, pV, NTOK, HID, HID, 0);

    // fused attention (head-axis softmax)
    attn_kernel<<<dim3(64, 4), blk, ATTN_SMEM>>>(pQ, pK, pV, pO);

    // output projection, residual + LN1
    gemm_bias_kernel<<<g_h1, blk>>>(pO, Wo, bo, pF, NTOK, HID, HID, 0);
    ln_kernel<<<NTOK, blk>>>(pF, x, g1, b1, pX1);

    // FFN
    gemm_bias_kernel<<<g_h4, blk>>>(pX1, W1, c1, pH, NTOK, 4 * HID, HID, 1);
    gemm_bias_kernel<<<g_h1, blk>>>(pH, W2, c2, pF, NTOK, HID, 4 * HID, 0);

    // residual + LN2 -> output
    ln_kernel<<<NTOK, blk>>>(pF, pX1, g2, b2, out);
}

// round 4
// speedup vs baseline: 1.7496x; 1.7228x over previous
#include <cuda_runtime.h>
#include <cuda_bf16.h>
#include <stdint.h>
#include <math.h>

// ---------------- scratch buffers (static device memory, no allocs) ----------
#define NTOK 4096              // 4 * 1024 rows
#define HID  1024
__device__ float g_Q [NTOK * HID];
__device__ float g_K [NTOK * HID];
__device__ float g_V [NTOK * HID];
__device__ float g_O [NTOK * HID];
__device__ float g_X1[NTOK * HID];
__device__ float g_F [NTOK * HID];
__device__ float g_H [NTOK * 4 * HID];
__device__ __nv_bfloat16 g_Ah[NTOK * 4 * HID];   // split activations (hi)
__device__ __nv_bfloat16 g_Al[NTOK * 4 * HID];   // split activations (lo)
__device__ __nv_bfloat16 g_Bh[4 * HID * HID];    // transposed split weights (hi)
__device__ __nv_bfloat16 g_Bl[4 * HID * HID];    // transposed split weights (lo)

// ---------------- PTX helpers (all arch-neutral: no 'a'-gated features) ------
__device__ __forceinline__ uint32_t smem_u32(const void* p) {
    uint32_t a;
    asm("{ .reg .u64 t; cvta.to.shared.u64 t, %1; cvt.u32.u64 %0, t; }"
        : "=r"(a) : "l"(p));
    return a;
}

#define CP_ASYNC16(s, g) \
    asm volatile("cp.async.cg.shared.global [%0], [%1], 16;" :: "r"(s), "l"(g))
#define CP_COMMIT() asm volatile("cp.async.commit_group;" ::: "memory")
#define CP_WAIT(n)  asm volatile("cp.async.wait_group %0;" :: "n"(n) : "memory")

#define LDSM_X4(r, addr) \
    asm volatile("ldmatrix.sync.aligned.m8n8.x4.shared.b16 {%0,%1,%2,%3}, [%4];" \
        : "=r"((r)[0]), "=r"((r)[1]), "=r"((r)[2]), "=r"((r)[3]) : "r"(addr))

#define MMA16816(c, a, b0, b1) \
    asm volatile("mma.sync.aligned.m16n8k16.row.col.f32.bf16.bf16.f32 " \
        "{%0,%1,%2,%3}, {%4,%5,%6,%7}, {%8,%9}, {%0,%1,%2,%3};" \
        : "+f"((c)[0]), "+f"((c)[1]), "+f"((c)[2]), "+f"((c)[3]) \
        : "r"((a)[0]), "r"((a)[1]), "r"((a)[2]), "r"((a)[3]), "r"(b0), "r"(b1))

// packed f32x2
#define FMA2(d, a, b) asm("fma.rn.f32x2 %0, %1, %2, %0;" : "+l"(d) : "l"(a), "l"(b))
#define PACK2(out, x, y) asm("mov.b64 %0, {%1, %2};" : "=l"(out) : "f"(x), "f"(y))
#define UNPACK2(lo, hi, in) asm("mov.b64 {%0, %1}, %2;" : "=f"(lo), "=f"(hi) : "l"(in))

// ---------------- conversion kernels -----------------------------------------
// split fp32 -> bf16 hi/lo
__global__ __launch_bounds__(256) void split_kernel(
    const float* __restrict__ A, __nv_bfloat16* __restrict__ H,
    __nv_bfloat16* __restrict__ L, int n4)
{
    int i = blockIdx.x * 256 + threadIdx.x;
    if (i >= n4) return;
    float4 v = ((const float4*)A)[i];
    __nv_bfloat16 h0 = __float2bfloat16(v.x), h1 = __float2bfloat16(v.y);
    __nv_bfloat16 h2 = __float2bfloat16(v.z), h3 = __float2bfloat16(v.w);
    __nv_bfloat16 l0 = __float2bfloat16(v.x - __bfloat162float(h0));
    __nv_bfloat16 l1 = __float2bfloat16(v.y - __bfloat162float(h1));
    __nv_bfloat16 l2 = __float2bfloat16(v.z - __bfloat162float(h2));
    __nv_bfloat16 l3 = __float2bfloat16(v.w - __bfloat162float(h3));
    ((__nv_bfloat162*)H)[i * 2 + 0] = __nv_bfloat162(h0, h1);
    ((__nv_bfloat162*)H)[i * 2 + 1] = __nv_bfloat162(h2, h3);
    ((__nv_bfloat162*)L)[i * 2 + 0] = __nv_bfloat162(l0, l1);
    ((__nv_bfloat162*)L)[i * 2 + 1] = __nv_bfloat162(l2, l3);
}

// transpose + split: W [K x N] fp32 -> Bh/Bl [N x K] bf16
__global__ __launch_bounds__(256) void tsplit_kernel(
    const float* __restrict__ W, __nv_bfloat16* __restrict__ H,
    __nv_bfloat16* __restrict__ L, int K, int N)
{
    __shared__ float t[32][33];
    const int tx = threadIdx.x, ty = threadIdx.y;
    const int bk = blockIdx.y * 32, bn = blockIdx.x * 32;
    #pragma unroll
    for (int j = 0; j < 4; ++j)
        t[ty + j * 8][tx] = W[(size_t)(bk + ty + j * 8) * N + bn + tx];
    __syncthreads();
    #pragma unroll
    for (int j = 0; j < 4; ++j) {
        int r = ty + j * 8;
        float v = t[tx][r];
        __nv_bfloat16 h = __float2bfloat16(v);
        __nv_bfloat16 l = __float2bfloat16(v - __bfloat162float(h));
        size_t o = (size_t)(bn + r) * K + bk + tx;
        H[o] = h; L[o] = l;
    }
}

// ---------------- bf16-split tensor-core GEMM (mma.sync HMMA path) -----------
// C[M,N] = act(A[M,K] @ W[K,N] + bias). A as bf16 hi/lo [M,K] row-major,
// W as transposed bf16 hi/lo [N,K]. CTA tile 128x128, BK=32, 8 warps (2x4),
// each warp 64x32 as 4x4 m16n8k16 fragments. 3 MMAs per step: hh + hl + lh.
#define G_PART  8192                    // 128 rows x 32 bf16
#define G_STAGE (4 * G_PART)            // Ah | Al | Bh | Bl
#define G_SMEM  (2 * G_STAGE)           // 64 KB double buffer

__global__ __launch_bounds__(256, 1) void gemm_tc_kernel(
    const __nv_bfloat16* __restrict__ Ah, const __nv_bfloat16* __restrict__ Al,
    const __nv_bfloat16* __restrict__ Bh, const __nv_bfloat16* __restrict__ Bl,
    const float* __restrict__ bias, float* __restrict__ C,
    int M, int N, int K, int act)
{
    extern __shared__ char smem[];
    const uint32_t sb = smem_u32(smem);
    const int tid = threadIdx.x;
    const int wid = tid >> 5, lane = tid & 31;
    const int warp_m = wid >> 2, warp_n = wid & 3;
    const int bm = blockIdx.y * 128, bn = blockIdx.x * 128;

    float acc[4][4][4];
    #pragma unroll
    for (int i = 0; i < 4; ++i)
        #pragma unroll
        for (int j = 0; j < 4; ++j)
            #pragma unroll
            for (int r = 0; r < 4; ++r) acc[i][j][r] = 0.f;

    // per-thread ldmatrix addressing (xor swizzle on 16B chunks within 64B rows)
    const int swz = (lane & 7) >> 1;
    const int rA = warp_m * 64 + ((lane >> 3) & 1) * 8 + (lane & 7);
    const int kA = lane >> 4;
    const int rB = warp_n * 32 + (lane >> 4) * 8 + (lane & 7);
    const int kB = (lane >> 3) & 1;

    const int nst = K >> 5;

    // stage loader: 2048 16B-chunks per stage (512 per part), 8 cp.async/thread
    auto load_stage = [&](int j) {
        const uint32_t st = sb + (uint32_t)(j & 1) * G_STAGE;
        const int kc = j * 32;
        #pragma unroll
        for (int t = 0; t < 2; ++t) {
            int idx = tid + t * 256;
            int row = idx >> 2, ch = idx & 3;
            uint32_t so = (uint32_t)row * 64 + (uint32_t)((ch ^ ((row >> 1) & 3)) << 4);
            size_t ga = (size_t)(bm + row) * K + kc + ch * 8;
            size_t gb = (size_t)(bn + row) * K + kc + ch * 8;
            CP_ASYNC16(st + 0 * G_PART + so, Ah + ga);
            CP_ASYNC16(st + 1 * G_PART + so, Al + ga);
            CP_ASYNC16(st + 2 * G_PART + so, Bh + gb);
            CP_ASYNC16(st + 3 * G_PART + so, Bl + gb);
        }
        CP_COMMIT();
    };

    load_stage(0);

    for (int j = 0; j < nst; ++j) {
        if (j + 1 < nst) { load_stage(j + 1); CP_WAIT(1); }
        else             { CP_WAIT(0); }
        __syncthreads();

        const uint32_t st = sb + (uint32_t)(j & 1) * G_STAGE;
        #pragma unroll
        for (int ks = 0; ks < 2; ++ks) {
            uint32_t ah[4][4], al[4][4], bh[2][4], bl[2][4];
            #pragma unroll
            for (int mt = 0; mt < 4; ++mt) {
                uint32_t ao = (uint32_t)(rA + mt * 16) * 64
                            + (uint32_t)(((ks * 2 + kA) ^ swz) << 4);
                LDSM_X4(ah[mt], st + 0 * G_PART + ao);
                LDSM_X4(al[mt], st + 1 * G_PART + ao);
            }
            #pragma unroll
            for (int np = 0; np < 2; ++np) {
                uint32_t bo = (uint32_t)(rB + np * 16) * 64
                            + (uint32_t)(((ks * 2 + kB) ^ swz) << 4);
                LDSM_X4(bh[np], st + 2 * G_PART + bo);
                LDSM_X4(bl[np], st + 3 * G_PART + bo);
            }
            #pragma unroll
            for (int mt = 0; mt < 4; ++mt)
                #pragma unroll
                for (int nt = 0; nt < 4; ++nt) {
                    const uint32_t* bhp = &bh[nt >> 1][(nt & 1) * 2];
                    const uint32_t* blp = &bl[nt >> 1][(nt & 1) * 2];
                    MMA16816(acc[mt][nt], ah[mt], bhp[0], bhp[1]);
                    MMA16816(acc[mt][nt], ah[mt], blp[0], blp[1]);
                    MMA16816(acc[mt][nt], al[mt], bhp[0], bhp[1]);
                }
        }
        __syncthreads();   // stage (j&1) fully consumed before it is reloaded
    }

    // epilogue: c frag lane l -> rows (l>>2, l>>2+8), cols (l&3)*2, +1
    #pragma unroll
    for (int mt = 0; mt < 4; ++mt)
        #pragma unroll
        for (int nt = 0; nt < 4; ++nt) {
            int row0 = bm + warp_m * 64 + mt * 16 + (lane >> 2);
            int col  = bn + warp_n * 32 + nt * 8 + (lane & 3) * 2;
            float b0 = bias[col], b1 = bias[col + 1];
            float v[4];
            v[0] = acc[mt][nt][0] + b0;
            v[1] = acc[mt][nt][1] + b1;
            v[2] = acc[mt][nt][2] + b0;
            v[3] = acc[mt][nt][3] + b1;
            if (act) {
                #pragma unroll
                for (int r = 0; r < 4; ++r)
                    v[r] = 0.5f * v[r] * (1.f + erff(v[r] * 0.70710678118654752f));
            }
            *(float2*)&C[(size_t)row0 * N + col]       = make_float2(v[0], v[1]);
            *(float2*)&C[(size_t)(row0 + 8) * N + col] = make_float2(v[2], v[3]);
        }
}

// ---------------- fused attention with head-axis softmax ---------------------
// q[n,h,t,d] = Q[n, h*64 + t/16, (t%16)*64 + d]  (raw reshape semantics)
// grid = (a=64, n=4), block = 256: h = tid>>4, bg = (tid>>3)&1, dq = tid&7.
#define SC(h, b, bp) ((h) * 272 + (b) * 17 + (bp))
#define BUFSTRIDE 1040

__global__ __launch_bounds__(256, 1) void attn_kernel(
    const float* __restrict__ Q, const float* __restrict__ K,
    const float* __restrict__ V, float* __restrict__ O)
{
    extern __shared__ float sm[];
    float* buf = sm;                       // 16*1040 floats
    float* sc  = sm + 16 * BUFSTRIDE;      // 16*272 floats

    const int tid = threadIdx.x;
    const int h  = tid >> 4;
    const int bg = (tid >> 3) & 1;
    const int dq = tid & 7;
    const int a = blockIdx.x;
    const int n = blockIdx.y;
    const float scale = 0.03125f;

    const size_t base_n = (size_t)n * 1024 * 1024;

    unsigned long long q2[8][4];
    #pragma unroll
    for (int i = 0; i < 8; ++i) {
        const float* qrow = Q + base_n + (size_t)(h * 64 + a) * 1024
                              + (bg * 8 + i) * 64;
        #pragma unroll
        for (int m = 0; m < 2; ++m) {
            float4 t = *(const float4*)(qrow + dq * 4 + m * 32);
            t.x *= scale; t.y *= scale; t.z *= scale; t.w *= scale;
            PACK2(q2[i][m * 2 + 0], t.x, t.y);
            PACK2(q2[i][m * 2 + 1], t.z, t.w);
        }
    }

    unsigned long long acc2[8][4];
    #pragma unroll
    for (int i = 0; i < 8; ++i)
        #pragma unroll
        for (int p = 0; p < 4; ++p) acc2[i][p] = 0ULL;

    for (int ap = 0; ap < 64; ++ap) {
        __syncthreads();

        #pragma unroll
        for (int i = 0; i < 16; ++i)
            *(float4*)&buf[i * BUFSTRIDE + tid * 4] =
                *(const float4*)(K + base_n + (size_t)(i * 64 + ap) * 1024 + tid * 4);
        __syncthreads();

        // scores
        {
            const float* kh = buf + h * BUFSTRIDE;
            #pragma unroll
            for (int bp = 0; bp < 16; ++bp) {
                unsigned long long kp[4];
                #pragma unroll
                for (int m = 0; m < 2; ++m) {
                    ulonglong2 kv = *(const ulonglong2*)(kh + bp * 64 + dq * 4 + m * 32);
                    kp[m * 2 + 0] = kv.x;
                    kp[m * 2 + 1] = kv.y;
                }
                unsigned long long s2[8];
                #pragma unroll
                for (int i = 0; i < 8; ++i) s2[i] = 0ULL;
                #pragma unroll
                for (int p = 0; p < 4; ++p)
                    #pragma unroll
                    for (int i = 0; i < 8; ++i)
                        FMA2(s2[i], q2[i][p], kp[p]);

                float sf[8];
                #pragma unroll
                for (int i = 0; i < 8; ++i) {
                    float lo, hi;
                    UNPACK2(lo, hi, s2[i]);
                    sf[i] = lo + hi;
                    sf[i] += __shfl_xor_sync(0xffffffffu, sf[i], 1);
                    sf[i] += __shfl_xor_sync(0xffffffffu, sf[i], 2);
                    sf[i] += __shfl_xor_sync(0xffffffffu, sf[i], 4);
                }
                float a0 = (dq & 1) ? sf[1] : sf[0];
                float a1 = (dq & 1) ? sf[3] : sf[2];
                float a2 = (dq & 1) ? sf[5] : sf[4];
                float a3 = (dq & 1) ? sf[7] : sf[6];
                float b0 = (dq & 2) ? a1 : a0;
                float b1 = (dq & 2) ? a3 : a2;
                float myv = (dq & 4) ? b1 : b0;
                sc[SC(h, bg * 8 + dq, bp)] = myv;
            }
        }
        __syncthreads();

        // stage V while doing head-softmax on sc
        #pragma unroll
        for (int i = 0; i < 16; ++i)
            *(float4*)&buf[i * BUFSTRIDE + tid * 4] =
                *(const float4*)(V + base_n + (size_t)(i * 64 + ap) * 1024 + tid * 4);

        {
            const int pb = tid >> 4, pbp = tid & 15;
            float m = -1e30f;
            #pragma unroll
            for (int hh = 0; hh < 16; ++hh) m = fmaxf(m, sc[SC(hh, pb, pbp)]);
            float e[16], ssum = 0.f;
            #pragma unroll
            for (int hh = 0; hh < 16; ++hh) {
                e[hh] = __expf(sc[SC(hh, pb, pbp)] - m);
                ssum += e[hh];
            }
            float inv = 1.f / ssum;
            #pragma unroll
            for (int hh = 0; hh < 16; ++hh) sc[SC(hh, pb, pbp)] = e[hh] * inv;
        }
        __syncthreads();

        // AV accumulate
        {
            const float* vh = buf + h * BUFSTRIDE;
            #pragma unroll
            for (int bp = 0; bp < 16; ++bp) {
                unsigned long long vp[4];
                #pragma unroll
                for (int m = 0; m < 2; ++m) {
                    ulonglong2 vv = *(const ulonglong2*)(vh + bp * 64 + dq * 4 + m * 32);
                    vp[m * 2 + 0] = vv.x;
                    vp[m * 2 + 1] = vv.y;
                }
                #pragma unroll
                for (int i = 0; i < 8; ++i) {
                    float w = sc[SC(h, bg * 8 + i, bp)];
                    unsigned long long w2;
                    PACK2(w2, w, w);
                    #pragma unroll
                    for (int p = 0; p < 4; ++p)
                        FMA2(acc2[i][p], w2, vp[p]);
                }
            }
        }
    }

    #pragma unroll
    for (int i = 0; i < 8; ++i) {
        float* orow = O + base_n + (size_t)(h * 64 + a) * 1024 + (bg * 8 + i) * 64;
        #pragma unroll
        for (int m = 0; m < 2; ++m) {
            ulonglong2 ov;
            ov.x = acc2[i][m * 2 + 0];
            ov.y = acc2[i][m * 2 + 1];
            *(ulonglong2*)(orow + dq * 4 + m * 32) = ov;
        }
    }
}

// ---------------- fused residual + LayerNorm ---------------------------------
__global__ __launch_bounds__(256) void ln_kernel(
    const float* __restrict__ A, const float* __restrict__ R,
    const float* __restrict__ g, const float* __restrict__ bta,
    float* __restrict__ out)
{
    __shared__ float red[16];
    const int row = blockIdx.x;
    const int tid = threadIdx.x;

    float4 v = ((const float4*)(A + (size_t)row * 1024))[tid];
    float4 r = ((const float4*)(R + (size_t)row * 1024))[tid];
    v.x += r.x; v.y += r.y; v.z += r.z; v.w += r.w;

    float s  = v.x + v.y + v.z + v.w;
    float sq = v.x * v.x + v.y * v.y + v.z * v.z + v.w * v.w;
    #pragma unroll
    for (int o = 16; o > 0; o >>= 1) {
        s  += __shfl_xor_sync(0xffffffffu, s,  o);
        sq += __shfl_xor_sync(0xffffffffu, sq, o);
    }
    if ((tid & 31) == 0) { red[tid >> 5] = s; red[8 + (tid >> 5)] = sq; }
    __syncthreads();
    float S = 0.f, SQ = 0.f;
    #pragma unroll
    for (int w = 0; w < 8; ++w) { S += red[w]; SQ += red[8 + w]; }

    const float mean = S * (1.f / 1024.f);
    const float var  = SQ * (1.f / 1024.f) - mean * mean;
    const float rstd = rsqrtf(var + 1e-5f);

    float4 gv = ((const float4*)g)[tid];
    float4 bv = ((const float4*)bta)[tid];
    float4 o;
    o.x = (v.x - mean) * rstd * gv.x + bv.x;
    o.y = (v.y - mean) * rstd * gv.y + bv.y;
    o.z = (v.z - mean) * rstd * gv.z + bv.z;
    o.w = (v.w - mean) * rstd * gv.w + bv.w;
    ((float4*)(out + (size_t)row * 1024))[tid] = o;
}

// ---------------- launch ------------------------------------------------------
extern "C" void kernel_launch(void* const* d_in, const int* in_sizes, int n_in,
                              void* d_out, int out_size)
{
    const float* x  = (const float*)d_in[0];
    const float* Wq = (const float*)d_in[1];
    const float* bq = (const float*)d_in[2];
    const float* Wk = (const float*)d_in[3];
    const float* bk = (const float*)d_in[4];
    const float* Wv = (const float*)d_in[5];
    const float* bv = (const float*)d_in[6];
    const float* Wo = (const float*)d_in[7];
    const float* bo = (const float*)d_in[8];
    const float* g1 = (const float*)d_in[9];
    const float* b1 = (const float*)d_in[10];
    const float* W1 = (const float*)d_in[11];
    const float* c1 = (const float*)d_in[12];
    const float* W2 = (const float*)d_in[13];
    const float* c2 = (const float*)d_in[14];
    const float* g2 = (const float*)d_in[15];
    const float* b2 = (const float*)d_in[16];
    float* out = (float*)d_out;

    float *pQ, *pK, *pV, *pO, *pX1, *pF, *pH;
    __nv_bfloat16 *pAh, *pAl, *pBh, *pBl;
    cudaGetSymbolAddress((void**)&pQ,  g_Q);
    cudaGetSymbolAddress((void**)&pK,  g_K);
    cudaGetSymbolAddress((void**)&pV,  g_V);
    cudaGetSymbolAddress((void**)&pO,  g_O);
    cudaGetSymbolAddress((void**)&pX1, g_X1);
    cudaGetSymbolAddress((void**)&pF,  g_F);
    cudaGetSymbolAddress((void**)&pH,  g_H);
    cudaGetSymbolAddress((void**)&pAh, g_Ah);
    cudaGetSymbolAddress((void**)&pAl, g_Al);
    cudaGetSymbolAddress((void**)&pBh, g_Bh);
    cudaGetSymbolAddress((void**)&pBl, g_Bl);

    const int ATTN_SMEM = (16 * BUFSTRIDE + 16 * 272) * 4;
    cudaFuncSetAttribute(attn_kernel, cudaFuncAttributeMaxDynamicSharedMemorySize, ATTN_SMEM);
    cudaFuncSetAttribute(gemm_tc_kernel, cudaFuncAttributeMaxDynamicSharedMemorySize, G_SMEM);

    dim3 blk(256);
    dim3 t32(32, 8);
    const int n4_1 = NTOK * HID / 4;
    const int n4_4 = NTOK * 4 * HID / 4;
    dim3 gs1((n4_1 + 255) / 256), gs4((n4_4 + 255) / 256);
    dim3 tg11(HID / 32, HID / 32);
    dim3 tg14(4 * HID / 32, HID / 32);
    dim3 tg41(HID / 32, 4 * HID / 32);
    dim3 gg1(HID / 128, NTOK / 128);
    dim3 gg4(4 * HID / 128, NTOK / 128);

    // QKV: split x once, transpose each weight, gemm
    split_kernel<<<gs1, blk>>>(x, pAh, pAl, n4_1);
    tsplit_kernel<<<tg11, t32>>>(Wq, pBh, pBl, HID, HID);
    gemm_tc_kernel<<<gg1, blk, G_SMEM>>>(pAh, pAl, pBh, pBl, bq, pQ, NTOK, HID, HID, 0);
    tsplit_kernel<<<tg11, t32>>>(Wk, pBh, pBl, HID, HID);
    gemm_tc_kernel<<<gg1, blk, G_SMEM>>>(pAh, pAl, pBh, pBl, bk, pK, NTOK, HID, HID, 0);
    tsplit_kernel<<<tg11, t32>>>(Wv, pBh, pBl, HID, HID);
    gemm_tc_kernel<<<gg1, blk, G_SMEM>>>(pAh, pAl, pBh, pBl, bv, pV, NTOK, HID, HID, 0);

    // fused attention (head-axis softmax)
    attn_kernel<<<dim3(64, 4), blk, ATTN_SMEM>>>(pQ, pK, pV, pO);

    // output projection, residual + LN1
    split_kernel<<<gs1, blk>>>(pO, pAh, pAl, n4_1);
    tsplit_kernel<<<tg11, t32>>>(Wo, pBh, pBl, HID, HID);
    gemm_tc_kernel<<<gg1, blk, G_SMEM>>>(pAh, pAl, pBh, pBl, bo, pF, NTOK, HID, HID, 0);
    ln_kernel<<<NTOK, blk>>>(pF, x, g1, b1, pX1);

    // FFN
    split_kernel<<<gs1, blk>>>(pX1, pAh, pAl, n4_1);
    tsplit_kernel<<<tg14, t32>>>(W1, pBh, pBl, HID, 4 * HID);
    gemm_tc_kernel<<<gg4, blk, G_SMEM>>>(pAh, pAl, pBh, pBl, c1, pH, NTOK, 4 * HID, HID, 1);
    split_kernel<<<gs4, blk>>>(pH, pAh, pAl, n4_4);
    tsplit_kernel<<<tg41, t32>>>(W2, pBh, pBl, 4 * HID, HID);
    gemm_tc_kernel<<<gg1, blk, G_SMEM>>>(pAh, pAl, pBh, pBl, c2, pF, NTOK, HID, 4 * HID, 0);

    // residual + LN2 -> output
    ln_kernel<<<NTOK, blk>>>(pF, pX1, g2, b2, out);
}